// round 15
// baseline (speedup 1.0000x reference)
#include <cuda_runtime.h>
#include <cuda_bf16.h>
#include <cstdint>

#define SEQ    2048
#define BATCH  512
#define INPT   64
#define HIDDEN 128
#define BB     4
#define NBLK   (BATCH / BB)    // 128 blocks, 1/SM
#define NTHR   256             // 8 warps
#define NKT    8               // serial k-tiles (K = HIDDEN = 128)

// 512MB scratch, TRANSPOSED: xp_T[j][t*BATCH+b] = x(t,b)@W_ih^T[j] + b_ih[j] + b_hh[j]
#define NROWS ((size_t)SEQ * BATCH)
__device__ float g_xp[(size_t)HIDDEN * NROWS];

__device__ __forceinline__ float tanh_fast(float z) {
    float az = fabsf(z);
    float e  = __expf(-2.0f * az);
    float r  = __fdividef(1.0f - e, 1.0f + e);
    return copysignf(r, z);
}
__device__ __forceinline__ void cp16(void* smem_dst, const float* gsrc) {
    unsigned dst = (unsigned)__cvta_generic_to_shared(smem_dst);
    asm volatile("cp.async.ca.shared.global [%0], [%1], 16;" :: "r"(dst), "l"(gsrc));
}
__device__ __forceinline__ void split_bf(float v, __nv_bfloat16& hi,
                                         __nv_bfloat16& lo) {
    hi = __float2bfloat16(v);
    lo = __float2bfloat16(v - __bfloat162float(hi));
}
__device__ __forceinline__ uint32_t pack2bf(__nv_bfloat16 a, __nv_bfloat16 b) {
    __nv_bfloat162 t(a, b);                 // a -> low 16 bits
    return *reinterpret_cast<uint32_t*>(&t);
}
__device__ __forceinline__ void mma16816(float* d, const uint32_t* a,
                                         uint32_t b0, uint32_t b1) {
    asm volatile(
        "mma.sync.aligned.m16n8k16.row.col.f32.bf16.bf16.f32 "
        "{%0,%1,%2,%3}, {%4,%5,%6,%7}, {%8,%9}, {%0,%1,%2,%3};"
        : "+f"(d[0]), "+f"(d[1]), "+f"(d[2]), "+f"(d[3])
        : "r"(a[0]), "r"(a[1]), "r"(a[2]), "r"(a[3]), "r"(b0), "r"(b1));
}

// ============================================================================
// Kernel 1: xp GEMM into xp_T. 2048 blocks x 256 thr; block = 512 rows.
// Warp w: A = W_ih rows [16w, 16w+16) in registers (4 kt, hi/lo).
// Iter: 8 x-rows (cp.async-staged), B-frags from smem, 12 HMMA,
// store via STG.64 (j-major layout -> sector-aligned, no amplification).
// ============================================================================
#define XRPB   512
#define XITER  (XRPB / 8)               // 64
#define XBLK   ((int)(NROWS / XRPB))    // 2048

__global__ void __launch_bounds__(256, 1)
xproj_hmma(const float* __restrict__ xs,
           const float* __restrict__ W_ih,
           const float* __restrict__ b_ih,
           const float* __restrict__ b_hh) {
    __shared__ __align__(16) float xst[4][8][68];   // 4-slot ring, padded rows

    const int tid  = threadIdx.x;
    const int wid  = tid >> 5;
    const int lane = tid & 31;
    const int g    = lane >> 2;
    const int q    = lane & 3;
    const size_t rb = (size_t)blockIdx.x * XRPB;

    const int jr0 = 16 * wid + g;
    const int jr1 = jr0 + 8;

    // A fragments: W_ih, 4 k-tiles, hi/lo split (32 regs)
    uint32_t aH[4][4], aL[4][4];
    #pragma unroll
    for (int kt = 0; kt < 4; kt++) {
        int c0 = kt * 16 + 2 * q;
        float w00 = W_ih[jr0 * INPT + c0];
        float w01 = W_ih[jr0 * INPT + c0 + 1];
        float w10 = W_ih[jr1 * INPT + c0];
        float w11 = W_ih[jr1 * INPT + c0 + 1];
        float w02 = W_ih[jr0 * INPT + c0 + 8];
        float w03 = W_ih[jr0 * INPT + c0 + 9];
        float w12 = W_ih[jr1 * INPT + c0 + 8];
        float w13 = W_ih[jr1 * INPT + c0 + 9];
        __nv_bfloat16 h, l, h2, l2;
        split_bf(w00, h, l); split_bf(w01, h2, l2);
        aH[kt][0] = pack2bf(h, h2); aL[kt][0] = pack2bf(l, l2);
        split_bf(w10, h, l); split_bf(w11, h2, l2);
        aH[kt][1] = pack2bf(h, h2); aL[kt][1] = pack2bf(l, l2);
        split_bf(w02, h, l); split_bf(w03, h2, l2);
        aH[kt][2] = pack2bf(h, h2); aL[kt][2] = pack2bf(l, l2);
        split_bf(w12, h, l); split_bf(w13, h2, l2);
        aH[kt][3] = pack2bf(h, h2); aL[kt][3] = pack2bf(l, l2);
    }
    const float bias0 = b_ih[jr0] + b_hh[jr0];
    const float bias1 = b_ih[jr1] + b_hh[jr1];

    // prologue: stage x for iters 0,1,2 (slots 0..2)
    #pragma unroll
    for (int s = 0; s < 3; s++) {
        if (tid < 128) {
            int row = tid >> 4, seg = tid & 15;
            cp16(&xst[s][row][seg * 4],
                 xs + (rb + s * 8 + row) * INPT + seg * 4);
        }
        asm volatile("cp.async.commit_group;" ::);
    }

    float* outJ0 = g_xp + (size_t)jr0 * NROWS + rb;
    float* outJ1 = g_xp + (size_t)jr1 * NROWS + rb;

    for (int it = 0; it < XITER; ++it) {
        asm volatile("cp.async.wait_group 2;" ::);   // slot it%4 ready
        __syncthreads();                             // all readers of it-1 done
        if (it + 3 < XITER && tid < 128) {
            int row = tid >> 4, seg = tid & 15;
            cp16(&xst[(it + 3) & 3][row][seg * 4],
                 xs + (rb + (size_t)(it + 3) * 8 + row) * INPT + seg * 4);
        }
        asm volatile("cp.async.commit_group;" ::);

        // B-frags from xst[it&3]; 12 HMMA, 3 chains of depth 4
        const float* xrow = &xst[it & 3][g][0];
        float D1[4] = {0, 0, 0, 0}, D2[4] = {0, 0, 0, 0}, D3[4] = {0, 0, 0, 0};
        #pragma unroll
        for (int kt = 0; kt < 4; kt++) {
            float2 v0 = *reinterpret_cast<const float2*>(xrow + kt * 16 + 2 * q);
            float2 v1 = *reinterpret_cast<const float2*>(xrow + kt * 16 + 8 + 2 * q);
            __nv_bfloat16 h0, l0, h1, l1;
            split_bf(v0.x, h0, l0); split_bf(v0.y, h1, l1);
            uint32_t bh0 = pack2bf(h0, h1), bl0 = pack2bf(l0, l1);
            split_bf(v1.x, h0, l0); split_bf(v1.y, h1, l1);
            uint32_t bh1 = pack2bf(h0, h1), bl1 = pack2bf(l0, l1);
            mma16816(D1, aH[kt], bh0, bh1);
            mma16816(D2, aL[kt], bh0, bh1);
            mma16816(D3, aH[kt], bl0, bl1);
        }

        // store: lane holds (jr0 / jr1) x rows (r0+2q, r0+2q+1) -> STG.64
        size_t r0 = (size_t)it * 8 + 2 * q;
        float2 o0, o1;
        o0.x = D1[0] + D2[0] + D3[0] + bias0;
        o0.y = D1[1] + D2[1] + D3[1] + bias0;
        o1.x = D1[2] + D2[2] + D3[2] + bias1;
        o1.y = D1[3] + D2[3] + D3[3] + bias1;
        *reinterpret_cast<float2*>(outJ0 + r0) = o0;
        *reinterpret_cast<float2*>(outJ1 + r0) = o1;
    }
}

// ============================================================================
// Kernel 2: serial recurrence over K=128 (R14 structure, frozen).
// Only change: xp staged from transposed layout; stage[s][j*4 + b].
// ============================================================================
__global__ void __launch_bounds__(NTHR, 1)
rnn_hmma_kernel(const float* __restrict__ W_hh,
                const float* __restrict__ W_out,
                const float* __restrict__ b_out,
                float* __restrict__ out) {
    __shared__ uint32_t uHi[2][64 * 8];
    __shared__ uint32_t uLo[2][64 * 8];
    __shared__ __align__(16) float stage[4][512];   // [slot][j*4 + b]
    __shared__ float red[BB][HIDDEN];

    const int tid  = threadIdx.x;
    const int wid  = tid >> 5;
    const int lane = tid & 31;
    const int g    = lane >> 2;
    const int q    = lane & 3;
    const long bbase = (long)blockIdx.x * BB;

    const int jr0 = 16 * wid + g;
    const int jr1 = jr0 + 8;
    const bool act = (q < 2);
    const int b0n = 2 * q;

    // A fragments (W_hh) in registers
    uint32_t aH[NKT][4], aL[NKT][4];
    #pragma unroll
    for (int kt = 0; kt < NKT; kt++) {
        int c0 = kt * 16 + 2 * q;
        float w00 = W_hh[jr0 * HIDDEN + c0];
        float w01 = W_hh[jr0 * HIDDEN + c0 + 1];
        float w10 = W_hh[jr1 * HIDDEN + c0];
        float w11 = W_hh[jr1 * HIDDEN + c0 + 1];
        float w02 = W_hh[jr0 * HIDDEN + c0 + 8];
        float w03 = W_hh[jr0 * HIDDEN + c0 + 9];
        float w12 = W_hh[jr1 * HIDDEN + c0 + 8];
        float w13 = W_hh[jr1 * HIDDEN + c0 + 9];
        __nv_bfloat16 h, l, h2, l2;
        split_bf(w00, h, l); split_bf(w01, h2, l2);
        aH[kt][0] = pack2bf(h, h2); aL[kt][0] = pack2bf(l, l2);
        split_bf(w10, h, l); split_bf(w11, h2, l2);
        aH[kt][1] = pack2bf(h, h2); aL[kt][1] = pack2bf(l, l2);
        split_bf(w02, h, l); split_bf(w03, h2, l2);
        aH[kt][2] = pack2bf(h, h2); aL[kt][2] = pack2bf(l, l2);
        split_bf(w12, h, l); split_bf(w13, h2, l2);
        aH[kt][3] = pack2bf(h, h2); aL[kt][3] = pack2bf(l, l2);
    }

    // h-store base (bf16 units) for (jr0, b0n)
    const int hidx = ((jr0 >> 1) * 8 + b0n) * 2 + (jr0 & 1);

    // init: h0 = 0; stage xp(0..2): one 16B chunk per j (4 batches)
    for (int i = tid; i < 2 * 64 * 8; i += NTHR) {
        (&uHi[0][0])[i] = 0u;
        (&uLo[0][0])[i] = 0u;
    }
    #pragma unroll
    for (int s = 0; s < 3; s++) {
        if (tid < 128) {
            cp16(&stage[s][tid * 4],
                 g_xp + (size_t)tid * NROWS + (size_t)s * BATCH + bbase);
        }
        asm volatile("cp.async.commit_group;" ::);
    }
    __syncthreads();

    for (int t = 0; t < SEQ - 1; ++t) {
        const int cur = t & 1, nxt = cur ^ 1;

        // prefetch xp(t+3) -> slot (t+3)&3
        if (t + 3 < SEQ && tid < 128) {
            cp16(&stage[(t + 3) & 3][tid * 4],
                 g_xp + (size_t)tid * NROWS + (size_t)(t + 3) * BATCH + bbase);
        }
        asm volatile("cp.async.commit_group;" ::);

        // ---- 24 HMMA: three chains of depth 8 ----
        float D1[4] = {0, 0, 0, 0}, D2[4] = {0, 0, 0, 0}, D3[4] = {0, 0, 0, 0};
        #pragma unroll
        for (int kt = 0; kt < NKT; kt++) {
            int wi = (kt * 8 + q) * 8 + g;
            uint32_t bh0 = uHi[cur][wi], bh1 = uHi[cur][wi + 32];
            uint32_t bl0 = uLo[cur][wi], bl1 = uLo[cur][wi + 32];
            mma16816(D1, aH[kt], bh0, bh1);
            mma16816(D2, aL[kt], bh0, bh1);
            mma16816(D3, aH[kt], bl0, bl1);
        }

        asm volatile("cp.async.wait_group 3;" ::);   // xp(t) ready

        // ---- epilogue: + xp, tanh, store h(t+1) ----
        if (act) {
            float xp00 = stage[t & 3][jr0 * 4 + b0n];
            float xp01 = stage[t & 3][jr0 * 4 + b0n + 1];
            float xp10 = stage[t & 3][jr1 * 4 + b0n];
            float xp11 = stage[t & 3][jr1 * 4 + b0n + 1];
            float h00 = tanh_fast(D1[0] + D2[0] + D3[0] + xp00);
            float h01 = tanh_fast(D1[1] + D2[1] + D3[1] + xp01);
            float h10 = tanh_fast(D1[2] + D2[2] + D3[2] + xp10);
            float h11 = tanh_fast(D1[3] + D2[3] + D3[3] + xp11);
            __nv_bfloat16* phN = reinterpret_cast<__nv_bfloat16*>(&uHi[nxt][0]);
            __nv_bfloat16* plN = reinterpret_cast<__nv_bfloat16*>(&uLo[nxt][0]);
            __nv_bfloat16 hh, ll;
            split_bf(h00, hh, ll); phN[hidx]      = hh; plN[hidx]      = ll;
            split_bf(h01, hh, ll); phN[hidx + 2]  = hh; plN[hidx + 2]  = ll;
            split_bf(h10, hh, ll); phN[hidx + 64] = hh; plN[hidx + 64] = ll;
            split_bf(h11, hh, ll); phN[hidx + 66] = hh; plN[hidx + 66] = ll;
        }
        __syncthreads();
    }

    // ---- peeled final step (t = SEQ-1): h_final -> red ----
    {
        const int t = SEQ - 1, cur = t & 1;
        asm volatile("cp.async.wait_group 0;" ::);
        float D1[4] = {0, 0, 0, 0}, D2[4] = {0, 0, 0, 0}, D3[4] = {0, 0, 0, 0};
        #pragma unroll
        for (int kt = 0; kt < NKT; kt++) {
            int wi = (kt * 8 + q) * 8 + g;
            uint32_t bh0 = uHi[cur][wi], bh1 = uHi[cur][wi + 32];
            uint32_t bl0 = uLo[cur][wi], bl1 = uLo[cur][wi + 32];
            mma16816(D1, aH[kt], bh0, bh1);
            mma16816(D2, aL[kt], bh0, bh1);
            mma16816(D3, aH[kt], bl0, bl1);
        }
        if (act) {
            red[b0n][jr0]     = tanh_fast(D1[0] + D2[0] + D3[0] + stage[t & 3][jr0 * 4 + b0n]);
            red[b0n + 1][jr0] = tanh_fast(D1[1] + D2[1] + D3[1] + stage[t & 3][jr0 * 4 + b0n + 1]);
            red[b0n][jr1]     = tanh_fast(D1[2] + D2[2] + D3[2] + stage[t & 3][jr1 * 4 + b0n]);
            red[b0n + 1][jr1] = tanh_fast(D1[3] + D2[3] + D3[3] + stage[t & 3][jr1 * 4 + b0n + 1]);
        }
        __syncthreads();
    }

    // ---- output projection ----
    if (wid < BB) {
        int b = wid;
        float s = 0.0f;
        #pragma unroll
        for (int m = 0; m < 4; m++) {
            int jj = lane + 32 * m;
            s += red[b][jj] * W_out[jj];
        }
        #pragma unroll
        for (int off = 16; off; off >>= 1)
            s += __shfl_down_sync(0xffffffffu, s, off);
        if (lane == 0) out[bbase + b] = s + b_out[0];
    }
}

extern "C" void kernel_launch(void* const* d_in, const int* in_sizes, int n_in,
                              void* d_out, int out_size) {
    const float* xs    = (const float*)d_in[0];
    const float* W_ih  = (const float*)d_in[1];
    const float* W_hh  = (const float*)d_in[2];
    const float* b_ih  = (const float*)d_in[3];
    const float* b_hh  = (const float*)d_in[4];
    const float* W_out = (const float*)d_in[5];
    const float* b_out = (const float*)d_in[6];

    xproj_hmma<<<XBLK, 256>>>(xs, W_ih, b_ih, b_hh);
    rnn_hmma_kernel<<<NBLK, NTHR>>>(W_hh, W_out, b_out, (float*)d_out);
}

// round 16
// speedup vs baseline: 1.2193x; 1.2193x over previous
#include <cuda_runtime.h>
#include <cuda_bf16.h>
#include <cstdint>

#define SEQ    2048
#define BATCH  512
#define INPT   64
#define HIDDEN 128
#define BB     4
#define NBLK   (BATCH / BB)    // 128 blocks, 1/SM
#define NTHR   256             // 8 warps
#define NKT    8               // serial k-tiles (K = HIDDEN = 128)

// 512MB scratch: xp[row][j], row = t*BATCH + b
#define NROWS ((size_t)SEQ * BATCH)
__device__ float g_xp[NROWS * HIDDEN];

__device__ __forceinline__ float tanh_fast(float z) {
    float az = fabsf(z);
    float e  = __expf(-2.0f * az);
    float r  = __fdividef(1.0f - e, 1.0f + e);
    return copysignf(r, z);
}
__device__ __forceinline__ void cp16(void* smem_dst, const float* gsrc) {
    unsigned dst = (unsigned)__cvta_generic_to_shared(smem_dst);
    asm volatile("cp.async.ca.shared.global [%0], [%1], 16;" :: "r"(dst), "l"(gsrc));
}
__device__ __forceinline__ void split_bf(float v, __nv_bfloat16& hi,
                                         __nv_bfloat16& lo) {
    hi = __float2bfloat16(v);
    lo = __float2bfloat16(v - __bfloat162float(hi));
}
__device__ __forceinline__ uint32_t pack2bf(__nv_bfloat16 a, __nv_bfloat16 b) {
    __nv_bfloat162 t(a, b);                 // a -> low 16 bits
    return *reinterpret_cast<uint32_t*>(&t);
}
__device__ __forceinline__ void mma16816(float* d, const uint32_t* a,
                                         uint32_t b0, uint32_t b1) {
    asm volatile(
        "mma.sync.aligned.m16n8k16.row.col.f32.bf16.bf16.f32 "
        "{%0,%1,%2,%3}, {%4,%5,%6,%7}, {%8,%9}, {%0,%1,%2,%3};"
        : "+f"(d[0]), "+f"(d[1]), "+f"(d[2]), "+f"(d[3])
        : "r"(a[0]), "r"(a[1]), "r"(a[2]), "r"(a[3]), "r"(b0), "r"(b1));
}

// ============================================================================
// Kernel 1: xp GEMM. 2048 blocks x 256 thr; block = 512 rows, 32 iters x 16.
// A = W_ih (registers, hi/lo). x converted to bf16 hi/lo ONCE per iter into
// smem (stride-12 bank-exact), warps do LDS + 24 HMMA + sector-aligned STG.
// smem word index for (kp, r8): kp*12 + r8  (all-distinct banks for both
// the converter STS pattern and the B-fragment LDS pattern).
// ============================================================================
#define XRPB   512
#define XITER  32
#define XBLK   ((int)(NROWS / XRPB))    // 2048

__global__ void __launch_bounds__(256, 1)
xproj_hmma(const float* __restrict__ xs,
           const float* __restrict__ W_ih,
           const float* __restrict__ b_ih,
           const float* __restrict__ b_hh) {
    __shared__ uint32_t xbh[2][2][384];   // [slot][ngroup][kp*12 + r8]
    __shared__ uint32_t xbl[2][2][384];

    const int tid  = threadIdx.x;
    const int wid  = tid >> 5;
    const int lane = tid & 31;
    const int g    = lane >> 2;
    const int q    = lane & 3;
    const size_t rb = (size_t)blockIdx.x * XRPB;

    const int jr0 = 16 * wid + g;
    const int jr1 = jr0 + 8;

    // A fragments: W_ih rows jr0/jr1, 4 k-tiles, hi/lo (32 regs)
    uint32_t aH[4][4], aL[4][4];
    #pragma unroll
    for (int kt = 0; kt < 4; kt++) {
        int c0 = kt * 16 + 2 * q;
        float w00 = W_ih[jr0 * INPT + c0];
        float w01 = W_ih[jr0 * INPT + c0 + 1];
        float w10 = W_ih[jr1 * INPT + c0];
        float w11 = W_ih[jr1 * INPT + c0 + 1];
        float w02 = W_ih[jr0 * INPT + c0 + 8];
        float w03 = W_ih[jr0 * INPT + c0 + 9];
        float w12 = W_ih[jr1 * INPT + c0 + 8];
        float w13 = W_ih[jr1 * INPT + c0 + 9];
        __nv_bfloat16 h, l, h2, l2;
        split_bf(w00, h, l); split_bf(w01, h2, l2);
        aH[kt][0] = pack2bf(h, h2); aL[kt][0] = pack2bf(l, l2);
        split_bf(w10, h, l); split_bf(w11, h2, l2);
        aH[kt][1] = pack2bf(h, h2); aL[kt][1] = pack2bf(l, l2);
        split_bf(w02, h, l); split_bf(w03, h2, l2);
        aH[kt][2] = pack2bf(h, h2); aL[kt][2] = pack2bf(l, l2);
        split_bf(w12, h, l); split_bf(w13, h2, l2);
        aH[kt][3] = pack2bf(h, h2); aL[kt][3] = pack2bf(l, l2);
    }
    const float bias0 = b_ih[jr0] + b_hh[jr0];
    const float bias1 = b_ih[jr1] + b_hh[jr1];

    // converter mapping: row16 = tid&15, cq = tid>>4; float4 at col cq*4
    const int row16 = tid & 15;
    const int cq    = tid >> 4;
    const int ngC   = row16 >> 3;
    const int r8C   = row16 & 7;
    const int kpC   = 2 * cq;

    auto convert_sts = [&](int slot, float4 xv) {
        __nv_bfloat16 h0, l0, h1, l1;
        split_bf(xv.x, h0, l0); split_bf(xv.y, h1, l1);
        xbh[slot][ngC][kpC * 12 + r8C]       = pack2bf(h0, h1);
        xbl[slot][ngC][kpC * 12 + r8C]       = pack2bf(l0, l1);
        split_bf(xv.z, h0, l0); split_bf(xv.w, h1, l1);
        xbh[slot][ngC][(kpC + 1) * 12 + r8C] = pack2bf(h0, h1);
        xbl[slot][ngC][(kpC + 1) * 12 + r8C] = pack2bf(l0, l1);
    };

    // prologue: load+convert iter 0 into slot 0
    float4 xv = *reinterpret_cast<const float4*>(
        xs + (rb + row16) * INPT + cq * 4);
    convert_sts(0, xv);
    __syncthreads();

    for (int it = 0; it < XITER; ++it) {
        const int s = it & 1;
        // load next iter's x (latency hidden under MMA below)
        if (it + 1 < XITER)
            xv = *reinterpret_cast<const float4*>(
                xs + (rb + (size_t)(it + 1) * 16 + row16) * INPT + cq * 4);

        // MMA on slot s, both 8-row groups
        #pragma unroll
        for (int ng = 0; ng < 2; ng++) {
            float D1[4] = {0, 0, 0, 0}, D2[4] = {0, 0, 0, 0}, D3[4] = {0, 0, 0, 0};
            #pragma unroll
            for (int kt = 0; kt < 4; kt++) {
                uint32_t bh0 = xbh[s][ng][(kt * 8 + q) * 12 + g];
                uint32_t bh1 = xbh[s][ng][(kt * 8 + q + 4) * 12 + g];
                uint32_t bl0 = xbl[s][ng][(kt * 8 + q) * 12 + g];
                uint32_t bl1 = xbl[s][ng][(kt * 8 + q + 4) * 12 + g];
                mma16816(D1, aH[kt], bh0, bh1);
                mma16816(D2, aL[kt], bh0, bh1);
                mma16816(D3, aH[kt], bl0, bl1);
            }
            // D rows = j (m-dim), cols = x-rows: d0/d1 -> rows 2q, 2q+1
            size_t r0 = rb + (size_t)it * 16 + ng * 8 + 2 * q;
            g_xp[r0 * HIDDEN + jr0]       = D1[0] + D2[0] + D3[0] + bias0;
            g_xp[(r0 + 1) * HIDDEN + jr0] = D1[1] + D2[1] + D3[1] + bias0;
            g_xp[r0 * HIDDEN + jr1]       = D1[2] + D2[2] + D3[2] + bias1;
            g_xp[(r0 + 1) * HIDDEN + jr1] = D1[3] + D2[3] + D3[3] + bias1;
        }

        // convert next iter into the other slot (readers of it-1 already done)
        if (it + 1 < XITER)
            convert_sts(s ^ 1, xv);
        __syncthreads();
    }
}

// ============================================================================
// Kernel 2: serial recurrence over K=128 — R14 version, FROZEN (932 us).
// ============================================================================
__global__ void __launch_bounds__(NTHR, 1)
rnn_hmma_kernel(const float* __restrict__ W_hh,
                const float* __restrict__ W_out,
                const float* __restrict__ b_out,
                float* __restrict__ out) {
    __shared__ uint32_t uHi[2][64 * 8];
    __shared__ uint32_t uLo[2][64 * 8];
    __shared__ __align__(16) float stage[4][BB][HIDDEN];   // 8 KB
    __shared__ float red[BB][HIDDEN];

    const int tid  = threadIdx.x;
    const int wid  = tid >> 5;
    const int lane = tid & 31;
    const int g    = lane >> 2;
    const int q    = lane & 3;
    const long bbase = (long)blockIdx.x * BB;

    const int jr0 = 16 * wid + g;
    const int jr1 = jr0 + 8;
    const bool act = (q < 2);
    const int b0n = 2 * q;

    // A fragments (W_hh) in registers: 8 kt x {hi,lo} x 4 regs
    uint32_t aH[NKT][4], aL[NKT][4];
    #pragma unroll
    for (int kt = 0; kt < NKT; kt++) {
        int c0 = kt * 16 + 2 * q;
        float w00 = W_hh[jr0 * HIDDEN + c0];
        float w01 = W_hh[jr0 * HIDDEN + c0 + 1];
        float w10 = W_hh[jr1 * HIDDEN + c0];
        float w11 = W_hh[jr1 * HIDDEN + c0 + 1];
        float w02 = W_hh[jr0 * HIDDEN + c0 + 8];
        float w03 = W_hh[jr0 * HIDDEN + c0 + 9];
        float w12 = W_hh[jr1 * HIDDEN + c0 + 8];
        float w13 = W_hh[jr1 * HIDDEN + c0 + 9];
        __nv_bfloat16 h, l, h2, l2;
        split_bf(w00, h, l); split_bf(w01, h2, l2);
        aH[kt][0] = pack2bf(h, h2); aL[kt][0] = pack2bf(l, l2);
        split_bf(w10, h, l); split_bf(w11, h2, l2);
        aH[kt][1] = pack2bf(h, h2); aL[kt][1] = pack2bf(l, l2);
        split_bf(w02, h, l); split_bf(w03, h2, l2);
        aH[kt][2] = pack2bf(h, h2); aL[kt][2] = pack2bf(l, l2);
        split_bf(w12, h, l); split_bf(w13, h2, l2);
        aH[kt][3] = pack2bf(h, h2); aL[kt][3] = pack2bf(l, l2);
    }

    // h-store base (bf16 units) for (jr0, b0n): kp = jr0>>1
    const int hidx = ((jr0 >> 1) * 8 + b0n) * 2 + (jr0 & 1);

    // init: h0 = 0; stage xp(0), xp(1), xp(2)
    for (int i = tid; i < 2 * 64 * 8; i += NTHR) {
        (&uHi[0][0])[i] = 0u;
        (&uLo[0][0])[i] = 0u;
    }
    #pragma unroll
    for (int s = 0; s < 3; s++) {
        if (tid < 128) {
            int b = tid >> 5, seg = tid & 31;
            cp16(&stage[s][b][seg * 4],
                 g_xp + ((size_t)s * BATCH + bbase + b) * HIDDEN + seg * 4);
        }
        asm volatile("cp.async.commit_group;" ::);
    }
    __syncthreads();

    for (int t = 0; t < SEQ - 1; ++t) {
        const int cur = t & 1, nxt = cur ^ 1;

        // prefetch xp(t+3) -> slot (t+3)&3
        if (t + 3 < SEQ && tid < 128) {
            int b = tid >> 5, seg = tid & 31;
            cp16(&stage[(t + 3) & 3][b][seg * 4],
                 g_xp + ((size_t)(t + 3) * BATCH + bbase + b) * HIDDEN + seg * 4);
        }
        asm volatile("cp.async.commit_group;" ::);

        // ---- 24 HMMA: three chains of depth 8 ----
        float D1[4] = {0, 0, 0, 0}, D2[4] = {0, 0, 0, 0}, D3[4] = {0, 0, 0, 0};
        #pragma unroll
        for (int kt = 0; kt < NKT; kt++) {
            int wi = (kt * 8 + q) * 8 + g;
            uint32_t bh0 = uHi[cur][wi], bh1 = uHi[cur][wi + 32];
            uint32_t bl0 = uLo[cur][wi], bl1 = uLo[cur][wi + 32];
            mma16816(D1, aH[kt], bh0, bh1);
            mma16816(D2, aL[kt], bh0, bh1);
            mma16816(D3, aH[kt], bl0, bl1);
        }

        asm volatile("cp.async.wait_group 3;" ::);   // xp(t) ready

        // ---- epilogue: + xp, tanh, store h(t+1) ----
        if (act) {
            float xp00 = stage[t & 3][b0n][jr0];
            float xp01 = stage[t & 3][b0n + 1][jr0];
            float xp10 = stage[t & 3][b0n][jr1];
            float xp11 = stage[t & 3][b0n + 1][jr1];
            float h00 = tanh_fast(D1[0] + D2[0] + D3[0] + xp00);
            float h01 = tanh_fast(D1[1] + D2[1] + D3[1] + xp01);
            float h10 = tanh_fast(D1[2] + D2[2] + D3[2] + xp10);
            float h11 = tanh_fast(D1[3] + D2[3] + D3[3] + xp11);
            __nv_bfloat16* phN = reinterpret_cast<__nv_bfloat16*>(&uHi[nxt][0]);
            __nv_bfloat16* plN = reinterpret_cast<__nv_bfloat16*>(&uLo[nxt][0]);
            __nv_bfloat16 hh, ll;
            split_bf(h00, hh, ll); phN[hidx]      = hh; plN[hidx]      = ll;
            split_bf(h01, hh, ll); phN[hidx + 2]  = hh; plN[hidx + 2]  = ll;
            split_bf(h10, hh, ll); phN[hidx + 64] = hh; plN[hidx + 64] = ll;
            split_bf(h11, hh, ll); phN[hidx + 66] = hh; plN[hidx + 66] = ll;
        }
        __syncthreads();
    }

    // ---- peeled final step (t = SEQ-1): h_final -> red ----
    {
        const int t = SEQ - 1, cur = t & 1;
        asm volatile("cp.async.wait_group 0;" ::);
        float D1[4] = {0, 0, 0, 0}, D2[4] = {0, 0, 0, 0}, D3[4] = {0, 0, 0, 0};
        #pragma unroll
        for (int kt = 0; kt < NKT; kt++) {
            int wi = (kt * 8 + q) * 8 + g;
            uint32_t bh0 = uHi[cur][wi], bh1 = uHi[cur][wi + 32];
            uint32_t bl0 = uLo[cur][wi], bl1 = uLo[cur][wi + 32];
            mma16816(D1, aH[kt], bh0, bh1);
            mma16816(D2, aL[kt], bh0, bh1);
            mma16816(D3, aH[kt], bl0, bl1);
        }
        if (act) {
            red[b0n][jr0]     = tanh_fast(D1[0] + D2[0] + D3[0] + stage[t & 3][b0n][jr0]);
            red[b0n + 1][jr0] = tanh_fast(D1[1] + D2[1] + D3[1] + stage[t & 3][b0n + 1][jr0]);
            red[b0n][jr1]     = tanh_fast(D1[2] + D2[2] + D3[2] + stage[t & 3][b0n][jr1]);
            red[b0n + 1][jr1] = tanh_fast(D1[3] + D2[3] + D3[3] + stage[t & 3][b0n + 1][jr1]);
        }
        __syncthreads();
    }

    // ---- output projection ----
    if (wid < BB) {
        int b = wid;
        float s = 0.0f;
        #pragma unroll
        for (int m = 0; m < 4; m++) {
            int jj = lane + 32 * m;
            s += red[b][jj] * W_out[jj];
        }
        #pragma unroll
        for (int off = 16; off; off >>= 1)
            s += __shfl_down_sync(0xffffffffu, s, off);
        if (lane == 0) out[bbase + b] = s + b_out[0];
    }
}

extern "C" void kernel_launch(void* const* d_in, const int* in_sizes, int n_in,
                              void* d_out, int out_size) {
    const float* xs    = (const float*)d_in[0];
    const float* W_ih  = (const float*)d_in[1];
    const float* W_hh  = (const float*)d_in[2];
    const float* b_ih  = (const float*)d_in[3];
    const float* b_hh  = (const float*)d_in[4];
    const float* W_out = (const float*)d_in[5];
    const float* b_out = (const float*)d_in[6];

    xproj_hmma<<<XBLK, 256>>>(xs, W_ih, b_ih, b_hh);
    rnn_hmma_kernel<<<NBLK, NTHR>>>(W_hh, W_out, b_out, (float*)d_out);
}